// round 10
// baseline (speedup 1.0000x reference)
#include <cuda_runtime.h>
#include <math.h>

#define Bb 2
#define Tt 2048
#define Cc 1024
#define Hh 16
#define Dd 64
#define BT (Bb*Tt)      // 4096
#define C3 (3*Cc)       // 3072
#define SPAD 68

// Scratch (allocation-free rule: __device__ globals)
__device__ float g_qkv[(size_t)BT * C3];           // [B,T,3C]
__device__ float g_att[(size_t)BT * Cc];           // attn_v in [B,T,C]

__device__ __forceinline__ unsigned f2tf(float x) {
    unsigned r;
    asm("cvt.rna.tf32.f32 %0, %1;" : "=r"(r) : "f"(x));
    return r;
}

#define MMA_TF32(c, a0,a1,a2,a3, b0,b1)                                   \
    asm volatile(                                                          \
        "mma.sync.aligned.m16n8k8.row.col.f32.tf32.tf32.f32 "             \
        "{%0,%1,%2,%3}, {%4,%5,%6,%7}, {%8,%9}, {%0,%1,%2,%3};"           \
        : "+f"((c)[0]), "+f"((c)[1]), "+f"((c)[2]), "+f"((c)[3])          \
        : "r"(a0), "r"(a1), "r"(a2), "r"(a3), "r"(b0), "r"(b1))

// ---------------------------------------------------------------------------
// TF32 tensor-core GEMM, double-buffered smem: one sync per k-tile, LDG for
// tile t+1 issued before the MMAs of tile t.
// out[M,N] = A[M,K] @ W[K,N] + bias[N]; BM=BN=128, BK=16, 8 warps.
// ---------------------------------------------------------------------------
__global__ __launch_bounds__(256) void gemm_tc_kernel(
    const float* __restrict__ A, const float* __restrict__ W,
    const float* __restrict__ bias, float* __restrict__ out,
    int M, int N, int K)
{
    __shared__ unsigned As[2][128][20];
    __shared__ unsigned Bs[2][16][132];

    const int tid  = threadIdx.x;
    const int warp = tid >> 5, lane = tid & 31;
    const int gID  = lane >> 2, tig = lane & 3;
    const int wm = (warp >> 2) * 64;
    const int wn = (warp & 3) * 32;
    const int row0 = blockIdx.y * 128;
    const int col0 = blockIdx.x * 128;

    const int aR = tid >> 2;
    const int aK = (tid & 3) * 4;
    const int bK = tid >> 4;
    const int bN = (tid & 15) * 8;

    const float* Ap  = A + (size_t)(row0 + aR) * K + aK;
    const float* Ap2 = Ap + (size_t)64 * K;
    const float* Wp  = W + (size_t)bK * N + col0 + bN;

    float acc[4][4][4];
#pragma unroll
    for (int mt = 0; mt < 4; mt++)
#pragma unroll
        for (int nt = 0; nt < 4; nt++)
#pragma unroll
            for (int i = 0; i < 4; i++) acc[mt][nt][i] = 0.f;

    const int ntile = K / 16;

    // tile 0 -> buffer 0
    {
        float4 pa0 = *(const float4*)(Ap);
        float4 pa1 = *(const float4*)(Ap2);
        float4 pb0 = *(const float4*)(Wp);
        float4 pb1 = *(const float4*)(Wp + 4);
        As[0][aR][aK+0] = f2tf(pa0.x); As[0][aR][aK+1] = f2tf(pa0.y);
        As[0][aR][aK+2] = f2tf(pa0.z); As[0][aR][aK+3] = f2tf(pa0.w);
        As[0][aR+64][aK+0] = f2tf(pa1.x); As[0][aR+64][aK+1] = f2tf(pa1.y);
        As[0][aR+64][aK+2] = f2tf(pa1.z); As[0][aR+64][aK+3] = f2tf(pa1.w);
        Bs[0][bK][bN+0] = f2tf(pb0.x); Bs[0][bK][bN+1] = f2tf(pb0.y);
        Bs[0][bK][bN+2] = f2tf(pb0.z); Bs[0][bK][bN+3] = f2tf(pb0.w);
        Bs[0][bK][bN+4] = f2tf(pb1.x); Bs[0][bK][bN+5] = f2tf(pb1.y);
        Bs[0][bK][bN+6] = f2tf(pb1.z); Bs[0][bK][bN+7] = f2tf(pb1.w);
    }
    __syncthreads();

    for (int t = 0; t < ntile; t++) {
        const int buf = t & 1;
        float4 pa0, pa1, pb0, pb1;
        const bool more = (t + 1 < ntile);
        if (more) {
            int k0 = (t + 1) * 16;
            pa0 = *(const float4*)(Ap + k0);
            pa1 = *(const float4*)(Ap2 + k0);
            pb0 = *(const float4*)(Wp + (size_t)k0 * N);
            pb1 = *(const float4*)(Wp + (size_t)k0 * N + 4);
        }

#pragma unroll
        for (int ks = 0; ks < 16; ks += 8) {
            unsigned af[4][4], bf[4][2];
#pragma unroll
            for (int mt = 0; mt < 4; mt++) {
                int r = wm + mt * 16 + gID;
                af[mt][0] = As[buf][r][ks + tig];
                af[mt][1] = As[buf][r + 8][ks + tig];
                af[mt][2] = As[buf][r][ks + tig + 4];
                af[mt][3] = As[buf][r + 8][ks + tig + 4];
            }
#pragma unroll
            for (int nt = 0; nt < 4; nt++) {
                int c = wn + nt * 8 + gID;
                bf[nt][0] = Bs[buf][ks + tig][c];
                bf[nt][1] = Bs[buf][ks + tig + 4][c];
            }
#pragma unroll
            for (int mt = 0; mt < 4; mt++)
#pragma unroll
                for (int nt = 0; nt < 4; nt++)
                    MMA_TF32(acc[mt][nt], af[mt][0], af[mt][1], af[mt][2], af[mt][3],
                             bf[nt][0], bf[nt][1]);
        }

        if (more) {
            const int nb = buf ^ 1;
            As[nb][aR][aK+0] = f2tf(pa0.x); As[nb][aR][aK+1] = f2tf(pa0.y);
            As[nb][aR][aK+2] = f2tf(pa0.z); As[nb][aR][aK+3] = f2tf(pa0.w);
            As[nb][aR+64][aK+0] = f2tf(pa1.x); As[nb][aR+64][aK+1] = f2tf(pa1.y);
            As[nb][aR+64][aK+2] = f2tf(pa1.z); As[nb][aR+64][aK+3] = f2tf(pa1.w);
            Bs[nb][bK][bN+0] = f2tf(pb0.x); Bs[nb][bK][bN+1] = f2tf(pb0.y);
            Bs[nb][bK][bN+2] = f2tf(pb0.z); Bs[nb][bK][bN+3] = f2tf(pb0.w);
            Bs[nb][bK][bN+4] = f2tf(pb1.x); Bs[nb][bK][bN+5] = f2tf(pb1.y);
            Bs[nb][bK][bN+6] = f2tf(pb1.z); Bs[nb][bK][bN+7] = f2tf(pb1.w);
            __syncthreads();
        }
    }

#pragma unroll
    for (int mt = 0; mt < 4; mt++) {
        int r = row0 + wm + mt * 16 + gID;
#pragma unroll
        for (int nt = 0; nt < 4; nt++) {
            int c = col0 + wn + nt * 8 + 2 * tig;
            float b0v = bias[c], b1v = bias[c + 1];
            float2 v0 = {acc[mt][nt][0] + b0v, acc[mt][nt][1] + b1v};
            float2 v1 = {acc[mt][nt][2] + b0v, acc[mt][nt][3] + b1v};
            *(float2*)(out + (size_t)r * N + c) = v0;
            *(float2*)(out + (size_t)(r + 8) * N + c) = v1;
        }
    }
}

// ---------------------------------------------------------------------------
// TF32 tensor-core flash attention with FUSED normalization.
// Block = (b, h, 128-query tile), 8 warps. Mainloop writes raw scores to
// attn_w; after the loop the block sweeps its own 128xTt slab of attn_w,
// applying exp(s-m)/l on the causal region and zeros above the diagonal.
// ---------------------------------------------------------------------------
__global__ __launch_bounds__(256) void attn_tc_kernel(
    const float* __restrict__ qkv,
    float* __restrict__ attn_w,
    float* __restrict__ att_out,
    int write_attn)
{
    extern __shared__ unsigned smu[];
    unsigned* Qs = smu;                  // [128][SPAD]  Q[q][d] (pre-scaled)
    unsigned* Ks = Qs + 128 * SPAD;      // [64][SPAD]   K[j][d]
    unsigned* Vs = Ks + 64 * SPAD;       // [64][SPAD]   V[j][d]
    unsigned* Ps = Vs + 64 * SPAD;       // [128][SPAD]  P[q][j]; later (m,l) table

    const int tid  = threadIdx.x;
    const int warp = tid >> 5, lane = tid & 31;
    const int gID  = lane >> 2, tig = lane & 3;
    const int qt = (Tt / 128 - 1) - blockIdx.x;   // heavy tiles first
    const int h  = blockIdx.y;
    const int b  = blockIdx.z;
    const int q0 = qt * 128;
    const int row_w = warp * 16;

    const float* Qg = qkv + ((size_t)b * Tt + q0) * C3 + h * Dd;
    const float* Kg = qkv + (size_t)b * Tt * C3 + Cc + h * Dd;
    const float* Vg = qkv + (size_t)b * Tt * C3 + 2 * Cc + h * Dd;

    for (int idx = tid; idx < 2048; idx += 256) {
        int q = idx >> 4, dc = (idx & 15) << 2;
        float4 v = *(const float4*)(Qg + (size_t)q * C3 + dc);
        unsigned* p = Qs + q * SPAD + dc;
        p[0] = f2tf(v.x * 0.125f); p[1] = f2tf(v.y * 0.125f);
        p[2] = f2tf(v.z * 0.125f); p[3] = f2tf(v.w * 0.125f);
    }

    float m0 = -1e30f, m1 = -1e30f, l0 = 0.f, l1 = 0.f;
    float o[8][4];
#pragma unroll
    for (int nt = 0; nt < 8; nt++)
#pragma unroll
        for (int i = 0; i < 4; i++) o[nt][i] = 0.f;

    const int r0g = q0 + row_w + gID;
    const int r1g = r0g + 8;
    const size_t slab = ((size_t)(b * Hh + h) * Tt + q0) * (size_t)Tt;
    const size_t wrow0 = slab + (size_t)(row_w + gID) * Tt;
    const size_t wrow1 = wrow0 + 8 * (size_t)Tt;

    const int nkt = 2 * qt + 2;
    for (int kt = 0; kt < nkt; kt++) {
        const int j0 = kt * 64;
        __syncthreads();
        for (int idx = tid; idx < 1024; idx += 256) {
            int j = idx >> 4, dc = (idx & 15) << 2;
            float4 kv = *(const float4*)(Kg + (size_t)(j0 + j) * C3 + dc);
            float4 vv = *(const float4*)(Vg + (size_t)(j0 + j) * C3 + dc);
            unsigned* kp = Ks + j * SPAD + dc;
            unsigned* vp = Vs + j * SPAD + dc;
            kp[0] = f2tf(kv.x); kp[1] = f2tf(kv.y); kp[2] = f2tf(kv.z); kp[3] = f2tf(kv.w);
            vp[0] = f2tf(vv.x); vp[1] = f2tf(vv.y); vp[2] = f2tf(vv.z); vp[3] = f2tf(vv.w);
        }
        __syncthreads();

        float s[8][4];
#pragma unroll
        for (int nt = 0; nt < 8; nt++)
#pragma unroll
            for (int i = 0; i < 4; i++) s[nt][i] = 0.f;
#pragma unroll
        for (int ks = 0; ks < 8; ks++) {
            unsigned a0 = Qs[(row_w + gID) * SPAD + ks * 8 + tig];
            unsigned a1 = Qs[(row_w + gID + 8) * SPAD + ks * 8 + tig];
            unsigned a2 = Qs[(row_w + gID) * SPAD + ks * 8 + tig + 4];
            unsigned a3 = Qs[(row_w + gID + 8) * SPAD + ks * 8 + tig + 4];
#pragma unroll
            for (int nt = 0; nt < 8; nt++) {
                unsigned b0 = Ks[(nt * 8 + gID) * SPAD + ks * 8 + tig];
                unsigned b1 = Ks[(nt * 8 + gID) * SPAD + ks * 8 + tig + 4];
                MMA_TF32(s[nt], a0, a1, a2, a3, b0, b1);
            }
        }

        if (kt >= 2 * qt) {
#pragma unroll
            for (int nt = 0; nt < 8; nt++) {
                int c = j0 + nt * 8 + 2 * tig;
                if (c     > r0g) s[nt][0] = -1e30f;
                if (c + 1 > r0g) s[nt][1] = -1e30f;
                if (c     > r1g) s[nt][2] = -1e30f;
                if (c + 1 > r1g) s[nt][3] = -1e30f;
            }
        }

        if (write_attn) {
#pragma unroll
            for (int nt = 0; nt < 8; nt++) {
                int c = j0 + nt * 8 + 2 * tig;
                float2 v0 = {s[nt][0], s[nt][1]};
                float2 v1 = {s[nt][2], s[nt][3]};
                *(float2*)(attn_w + wrow0 + c) = v0;
                *(float2*)(attn_w + wrow1 + c) = v1;
            }
        }

        float tm0 = -1e30f, tm1 = -1e30f;
#pragma unroll
        for (int nt = 0; nt < 8; nt++) {
            tm0 = fmaxf(tm0, fmaxf(s[nt][0], s[nt][1]));
            tm1 = fmaxf(tm1, fmaxf(s[nt][2], s[nt][3]));
        }
        tm0 = fmaxf(tm0, __shfl_xor_sync(0xffffffffu, tm0, 1));
        tm0 = fmaxf(tm0, __shfl_xor_sync(0xffffffffu, tm0, 2));
        tm1 = fmaxf(tm1, __shfl_xor_sync(0xffffffffu, tm1, 1));
        tm1 = fmaxf(tm1, __shfl_xor_sync(0xffffffffu, tm1, 2));

        float mn0 = fmaxf(m0, tm0), mn1 = fmaxf(m1, tm1);
        float f0 = __expf(m0 - mn0), f1 = __expf(m1 - mn1);
        float rs0 = 0.f, rs1 = 0.f;
#pragma unroll
        for (int nt = 0; nt < 8; nt++) {
            s[nt][0] = __expf(s[nt][0] - mn0);
            s[nt][1] = __expf(s[nt][1] - mn0);
            s[nt][2] = __expf(s[nt][2] - mn1);
            s[nt][3] = __expf(s[nt][3] - mn1);
            rs0 += s[nt][0] + s[nt][1];
            rs1 += s[nt][2] + s[nt][3];
        }
        rs0 += __shfl_xor_sync(0xffffffffu, rs0, 1);
        rs0 += __shfl_xor_sync(0xffffffffu, rs0, 2);
        rs1 += __shfl_xor_sync(0xffffffffu, rs1, 1);
        rs1 += __shfl_xor_sync(0xffffffffu, rs1, 2);
        l0 = l0 * f0 + rs0;  m0 = mn0;
        l1 = l1 * f1 + rs1;  m1 = mn1;
#pragma unroll
        for (int nt = 0; nt < 8; nt++) {
            o[nt][0] *= f0; o[nt][1] *= f0;
            o[nt][2] *= f1; o[nt][3] *= f1;
        }

#pragma unroll
        for (int nt = 0; nt < 8; nt++) {
            uint2 p0 = {f2tf(s[nt][0]), f2tf(s[nt][1])};
            uint2 p1 = {f2tf(s[nt][2]), f2tf(s[nt][3])};
            *(uint2*)&Ps[(row_w + gID) * SPAD + nt * 8 + 2 * tig] = p0;
            *(uint2*)&Ps[(row_w + gID + 8) * SPAD + nt * 8 + 2 * tig] = p1;
        }
        __syncthreads();

#pragma unroll
        for (int ks = 0; ks < 8; ks++) {
            unsigned a0 = Ps[(row_w + gID) * SPAD + ks * 8 + tig];
            unsigned a1 = Ps[(row_w + gID + 8) * SPAD + ks * 8 + tig];
            unsigned a2 = Ps[(row_w + gID) * SPAD + ks * 8 + tig + 4];
            unsigned a3 = Ps[(row_w + gID + 8) * SPAD + ks * 8 + tig + 4];
#pragma unroll
            for (int nt = 0; nt < 8; nt++) {
                unsigned b0 = Vs[(ks * 8 + tig) * SPAD + nt * 8 + gID];
                unsigned b1 = Vs[(ks * 8 + tig + 4) * SPAD + nt * 8 + gID];
                MMA_TF32(o[nt], a0, a1, a2, a3, b0, b1);
            }
        }
    }

    // epilogue: attn_v output
    float invl0 = 1.f / l0, invl1 = 1.f / l1;
    float* op0 = att_out + ((size_t)b * Tt + r0g) * Cc + h * Dd;
    float* op1 = att_out + ((size_t)b * Tt + r1g) * Cc + h * Dd;
#pragma unroll
    for (int nt = 0; nt < 8; nt++) {
        int c = nt * 8 + 2 * tig;
        float2 v0 = {o[nt][0] * invl0, o[nt][1] * invl0};
        float2 v1 = {o[nt][2] * invl1, o[nt][3] * invl1};
        *(float2*)(op0 + c) = v0;
        *(float2*)(op1 + c) = v1;
    }

    // ---- fused normalization sweep over this block's 128xTt slab ----
    if (write_attn) {
        float* sml = (float*)Ps;           // [128][2] (m,l) table
        __syncthreads();                   // PV-mma reads of Ps done
        if (tig == 0) {
            sml[(row_w + gID) * 2]     = m0;
            sml[(row_w + gID) * 2 + 1] = l0;
            sml[(row_w + gID + 8) * 2]     = m1;
            sml[(row_w + gID + 8) * 2 + 1] = l1;
        }
        __syncthreads();

        const int cols4 = Tt / 4;          // 512 float4 chunks per row
        for (int idx = tid; idx < 128 * cols4; idx += 256) {
            int r  = idx >> 9;             // idx / cols4
            int c0 = (idx & 511) << 2;
            int rg = q0 + r;
            float* p = attn_w + slab + (size_t)r * Tt + c0;
            if (c0 > rg) {
                float4 z = {0.f, 0.f, 0.f, 0.f};
                *(float4*)p = z;
            } else {
                float mr = sml[r * 2];
                float il = 1.f / sml[r * 2 + 1];
                float4 sv = *(const float4*)p;
                float4 w;
                w.x = (c0 + 0 > rg) ? 0.f : __expf(sv.x - mr) * il;
                w.y = (c0 + 1 > rg) ? 0.f : __expf(sv.y - mr) * il;
                w.z = (c0 + 2 > rg) ? 0.f : __expf(sv.z - mr) * il;
                w.w = (c0 + 3 > rg) ? 0.f : __expf(sv.w - mr) * il;
                *(float4*)p = w;
            }
        }
    }
}

// ---------------------------------------------------------------------------
extern "C" void kernel_launch(void* const* d_in, const int* in_sizes, int n_in,
                              void* d_out, int out_size)
{
    const float* x     = (const float*)d_in[0];
    const float* w_qkv = (const float*)d_in[1];
    const float* b_qkv = (const float*)d_in[2];
    const float* w_o   = (const float*)d_in[3];
    const float* b_o   = (const float*)d_in[4];
    float* out = (float*)d_out;

    float *qkv_ptr, *att_ptr;
    cudaGetSymbolAddress((void**)&qkv_ptr, g_qkv);
    cudaGetSymbolAddress((void**)&att_ptr, g_att);

    const size_t o_elems    = (size_t)Bb * Tt * Cc;
    const size_t attn_elems = (size_t)Bb * Hh * Tt * (size_t)Tt;
    int write_attn = ((size_t)out_size >= o_elems + attn_elems) ? 1 : 0;
    float* attn_w_ptr = write_attn ? (out + o_elems) : nullptr;

    const int attn_smem = (128 + 64 + 64 + 128) * SPAD * sizeof(unsigned); // 104448
    cudaFuncSetAttribute(attn_tc_kernel,
                         cudaFuncAttributeMaxDynamicSharedMemorySize, attn_smem);

    // 1) QKV projection (tf32 tensor cores, double-buffered)
    {
        dim3 grid(C3 / 128, BT / 128);
        gemm_tc_kernel<<<grid, 256>>>(x, w_qkv, b_qkv, qkv_ptr, BT, C3, Cc);
    }
    // 2) causal attention + fused normalization
    {
        dim3 grid(Tt / 128, Hh, Bb);
        attn_tc_kernel<<<grid, 256, attn_smem>>>(qkv_ptr, attn_w_ptr, att_ptr,
                                                 write_attn);
    }
    // 3) output projection (tf32 tensor cores, double-buffered)
    {
        dim3 grid(Cc / 128, BT / 128);
        gemm_tc_kernel<<<grid, 256>>>(att_ptr, w_o, b_o, out, BT, Cc, Cc);
    }
}

// round 11
// speedup vs baseline: 1.2408x; 1.2408x over previous
#include <cuda_runtime.h>
#include <math.h>

#define Bb 2
#define Tt 2048
#define Cc 1024
#define Hh 16
#define Dd 64
#define BT (Bb*Tt)      // 4096
#define C3 (3*Cc)       // 3072
#define SPAD 68

// Scratch (allocation-free rule: __device__ globals)
__device__ float g_qkv[(size_t)BT * C3];           // [B,T,3C]
__device__ float g_att[(size_t)BT * Cc];           // attn_v (tf32-rounded values)
__device__ float g_ml[(size_t)Bb * Hh * Tt * 2];   // per-row (m,l)
__device__ float g_x[(size_t)BT * Cc];             // tf32-rounded x
__device__ float g_wqkv[(size_t)Cc * C3];          // tf32-rounded w_qkv
__device__ float g_wo[(size_t)Cc * Cc];            // tf32-rounded w_o

__device__ __forceinline__ unsigned f2tf(float x) {
    unsigned r;
    asm("cvt.rna.tf32.f32 %0, %1;" : "=r"(r) : "f"(x));
    return r;
}

__device__ __forceinline__ void cp16(void* dst, const void* src) {
    unsigned d = (unsigned)__cvta_generic_to_shared(dst);
    asm volatile("cp.async.cg.shared.global [%0], [%1], 16;" :: "r"(d), "l"(src));
}
#define CP_COMMIT() asm volatile("cp.async.commit_group;")
#define CP_WAIT1()  asm volatile("cp.async.wait_group 1;")

#define MMA_TF32(c, a0,a1,a2,a3, b0,b1)                                   \
    asm volatile(                                                          \
        "mma.sync.aligned.m16n8k8.row.col.f32.tf32.tf32.f32 "             \
        "{%0,%1,%2,%3}, {%4,%5,%6,%7}, {%8,%9}, {%0,%1,%2,%3};"           \
        : "+f"((c)[0]), "+f"((c)[1]), "+f"((c)[2]), "+f"((c)[3])          \
        : "r"(a0), "r"(a1), "r"(a2), "r"(a3), "r"(b0), "r"(b1))

// ---------------------------------------------------------------------------
// Pre-round fp32 -> tf32-exact fp32 (RNA). n multiple of 1024.
// ---------------------------------------------------------------------------
__global__ __launch_bounds__(256) void round_tf32_kernel(
    const float* __restrict__ in, float* __restrict__ outp, int n)
{
    int i = (blockIdx.x * 256 + threadIdx.x) * 4;
    if (i < n) {
        float4 v = *(const float4*)(in + i);
        v.x = __uint_as_float(f2tf(v.x));
        v.y = __uint_as_float(f2tf(v.y));
        v.z = __uint_as_float(f2tf(v.z));
        v.w = __uint_as_float(f2tf(v.w));
        *(float4*)(outp + i) = v;
    }
}

// ---------------------------------------------------------------------------
// TF32 tensor-core GEMM, cp.async 3-stage pipeline, zero in-loop conversion.
// Operands MUST be tf32-exact fp32 (pre-rounded); HW truncation is then exact.
// out[M,N] = A[M,K] @ W[K,N] + bias[N]; BM=BN=128, BK=16, 8 warps.
// ---------------------------------------------------------------------------
__global__ __launch_bounds__(256) void gemm_tc_kernel(
    const float* __restrict__ A, const float* __restrict__ W,
    const float* __restrict__ bias, float* __restrict__ out,
    int M, int N, int K)
{
    __shared__ float As[3][128][20];
    __shared__ float Bs[3][16][132];

    const int tid  = threadIdx.x;
    const int warp = tid >> 5, lane = tid & 31;
    const int gID  = lane >> 2, tig = lane & 3;
    const int wm = (warp >> 2) * 64;
    const int wn = (warp & 3) * 32;
    const int row0 = blockIdx.y * 128;
    const int col0 = blockIdx.x * 128;

    const int aR = tid >> 2;
    const int aK = (tid & 3) * 4;
    const int bK = tid >> 4;
    const int bN = (tid & 15) * 8;

    const float* Ap  = A + (size_t)(row0 + aR) * K + aK;
    const float* Ap2 = Ap + (size_t)64 * K;
    const float* Wp  = W + (size_t)bK * N + col0 + bN;

    float acc[4][4][4];
#pragma unroll
    for (int mt = 0; mt < 4; mt++)
#pragma unroll
        for (int nt = 0; nt < 4; nt++)
#pragma unroll
            for (int i = 0; i < 4; i++) acc[mt][nt][i] = 0.f;

    const int ntile = K / 16;

    // prologue: stages 0 and 1
#pragma unroll
    for (int p = 0; p < 2; p++) {
        int k0 = p * 16;
        cp16(&As[p][aR][aK], Ap + k0);
        cp16(&As[p][aR + 64][aK], Ap2 + k0);
        cp16(&Bs[p][bK][bN], Wp + (size_t)k0 * N);
        cp16(&Bs[p][bK][bN + 4], Wp + (size_t)k0 * N + 4);
        CP_COMMIT();
    }

    int buf = 0;
    for (int t = 0; t < ntile; t++) {
        CP_WAIT1();
        __syncthreads();

        // prefetch t+2 into the slot consumed at t-1
        if (t + 2 < ntile) {
            int slot = (buf + 2) % 3;
            int k0 = (t + 2) * 16;
            cp16(&As[slot][aR][aK], Ap + k0);
            cp16(&As[slot][aR + 64][aK], Ap2 + k0);
            cp16(&Bs[slot][bK][bN], Wp + (size_t)k0 * N);
            cp16(&Bs[slot][bK][bN + 4], Wp + (size_t)k0 * N + 4);
        }
        CP_COMMIT();   // empty group in tail keeps wait-count math valid

#pragma unroll
        for (int ks = 0; ks < 16; ks += 8) {
            unsigned af[4][4], bf[4][2];
#pragma unroll
            for (int mt = 0; mt < 4; mt++) {
                int r = wm + mt * 16 + gID;
                af[mt][0] = __float_as_uint(As[buf][r][ks + tig]);
                af[mt][1] = __float_as_uint(As[buf][r + 8][ks + tig]);
                af[mt][2] = __float_as_uint(As[buf][r][ks + tig + 4]);
                af[mt][3] = __float_as_uint(As[buf][r + 8][ks + tig + 4]);
            }
#pragma unroll
            for (int nt = 0; nt < 4; nt++) {
                int c = wn + nt * 8 + gID;
                bf[nt][0] = __float_as_uint(Bs[buf][ks + tig][c]);
                bf[nt][1] = __float_as_uint(Bs[buf][ks + tig + 4][c]);
            }
#pragma unroll
            for (int mt = 0; mt < 4; mt++)
#pragma unroll
                for (int nt = 0; nt < 4; nt++)
                    MMA_TF32(acc[mt][nt], af[mt][0], af[mt][1], af[mt][2], af[mt][3],
                             bf[nt][0], bf[nt][1]);
        }
        buf = (buf + 1) % 3;
    }

#pragma unroll
    for (int mt = 0; mt < 4; mt++) {
        int r = row0 + wm + mt * 16 + gID;
#pragma unroll
        for (int nt = 0; nt < 4; nt++) {
            int c = col0 + wn + nt * 8 + 2 * tig;
            float b0v = bias[c], b1v = bias[c + 1];
            float2 v0 = {acc[mt][nt][0] + b0v, acc[mt][nt][1] + b1v};
            float2 v1 = {acc[mt][nt][2] + b0v, acc[mt][nt][3] + b1v};
            *(float2*)(out + (size_t)r * N + c) = v0;
            *(float2*)(out + (size_t)(r + 8) * N + c) = v1;
        }
    }
}

// ---------------------------------------------------------------------------
// TF32 tensor-core flash attention (R8 structure: raw scores + (m,l) out).
// Block = (b, h, 128-query tile), 8 warps. att_out written tf32-rounded so
// the projection GEMM's HW truncation is exact RNA.
// ---------------------------------------------------------------------------
__global__ __launch_bounds__(256) void attn_tc_kernel(
    const float* __restrict__ qkv,
    float* __restrict__ attn_w,
    float* __restrict__ att_out,
    float* __restrict__ ml,
    int write_attn)
{
    extern __shared__ unsigned smu[];
    unsigned* Qs = smu;                  // [128][SPAD]
    unsigned* Ks = Qs + 128 * SPAD;      // [64][SPAD]
    unsigned* Vs = Ks + 64 * SPAD;       // [64][SPAD]
    unsigned* Ps = Vs + 64 * SPAD;       // [128][SPAD]

    const int tid  = threadIdx.x;
    const int warp = tid >> 5, lane = tid & 31;
    const int gID  = lane >> 2, tig = lane & 3;
    const int qt = (Tt / 128 - 1) - blockIdx.x;
    const int h  = blockIdx.y;
    const int b  = blockIdx.z;
    const int q0 = qt * 128;
    const int row_w = warp * 16;

    const float* Qg = qkv + ((size_t)b * Tt + q0) * C3 + h * Dd;
    const float* Kg = qkv + (size_t)b * Tt * C3 + Cc + h * Dd;
    const float* Vg = qkv + (size_t)b * Tt * C3 + 2 * Cc + h * Dd;

    for (int idx = tid; idx < 2048; idx += 256) {
        int q = idx >> 4, dc = (idx & 15) << 2;
        float4 v = *(const float4*)(Qg + (size_t)q * C3 + dc);
        unsigned* p = Qs + q * SPAD + dc;
        p[0] = f2tf(v.x * 0.125f); p[1] = f2tf(v.y * 0.125f);
        p[2] = f2tf(v.z * 0.125f); p[3] = f2tf(v.w * 0.125f);
    }

    float m0 = -1e30f, m1 = -1e30f, l0 = 0.f, l1 = 0.f;
    float o[8][4];
#pragma unroll
    for (int nt = 0; nt < 8; nt++)
#pragma unroll
        for (int i = 0; i < 4; i++) o[nt][i] = 0.f;

    const int r0g = q0 + row_w + gID;
    const int r1g = r0g + 8;
    const size_t wrow0 = ((size_t)(b * Hh + h) * Tt + r0g) * (size_t)Tt;
    const size_t wrow1 = wrow0 + 8 * (size_t)Tt;

    const int nkt = 2 * qt + 2;
    for (int kt = 0; kt < nkt; kt++) {
        const int j0 = kt * 64;
        __syncthreads();
        for (int idx = tid; idx < 1024; idx += 256) {
            int j = idx >> 4, dc = (idx & 15) << 2;
            float4 kv = *(const float4*)(Kg + (size_t)(j0 + j) * C3 + dc);
            float4 vv = *(const float4*)(Vg + (size_t)(j0 + j) * C3 + dc);
            unsigned* kp = Ks + j * SPAD + dc;
            unsigned* vp = Vs + j * SPAD + dc;
            kp[0] = f2tf(kv.x); kp[1] = f2tf(kv.y); kp[2] = f2tf(kv.z); kp[3] = f2tf(kv.w);
            vp[0] = f2tf(vv.x); vp[1] = f2tf(vv.y); vp[2] = f2tf(vv.z); vp[3] = f2tf(vv.w);
        }
        __syncthreads();

        float s[8][4];
#pragma unroll
        for (int nt = 0; nt < 8; nt++)
#pragma unroll
            for (int i = 0; i < 4; i++) s[nt][i] = 0.f;
#pragma unroll
        for (int ks = 0; ks < 8; ks++) {
            unsigned a0 = Qs[(row_w + gID) * SPAD + ks * 8 + tig];
            unsigned a1 = Qs[(row_w + gID + 8) * SPAD + ks * 8 + tig];
            unsigned a2 = Qs[(row_w + gID) * SPAD + ks * 8 + tig + 4];
            unsigned a3 = Qs[(row_w + gID + 8) * SPAD + ks * 8 + tig + 4];
#pragma unroll
            for (int nt = 0; nt < 8; nt++) {
                unsigned b0 = Ks[(nt * 8 + gID) * SPAD + ks * 8 + tig];
                unsigned b1 = Ks[(nt * 8 + gID) * SPAD + ks * 8 + tig + 4];
                MMA_TF32(s[nt], a0, a1, a2, a3, b0, b1);
            }
        }

        if (kt >= 2 * qt) {
#pragma unroll
            for (int nt = 0; nt < 8; nt++) {
                int c = j0 + nt * 8 + 2 * tig;
                if (c     > r0g) s[nt][0] = -1e30f;
                if (c + 1 > r0g) s[nt][1] = -1e30f;
                if (c     > r1g) s[nt][2] = -1e30f;
                if (c + 1 > r1g) s[nt][3] = -1e30f;
            }
        }

        if (write_attn) {
#pragma unroll
            for (int nt = 0; nt < 8; nt++) {
                int c = j0 + nt * 8 + 2 * tig;
                float2 v0 = {s[nt][0], s[nt][1]};
                float2 v1 = {s[nt][2], s[nt][3]};
                *(float2*)(attn_w + wrow0 + c) = v0;
                *(float2*)(attn_w + wrow1 + c) = v1;
            }
        }

        float tm0 = -1e30f, tm1 = -1e30f;
#pragma unroll
        for (int nt = 0; nt < 8; nt++) {
            tm0 = fmaxf(tm0, fmaxf(s[nt][0], s[nt][1]));
            tm1 = fmaxf(tm1, fmaxf(s[nt][2], s[nt][3]));
        }
        tm0 = fmaxf(tm0, __shfl_xor_sync(0xffffffffu, tm0, 1));
        tm0 = fmaxf(tm0, __shfl_xor_sync(0xffffffffu, tm0, 2));
        tm1 = fmaxf(tm1, __shfl_xor_sync(0xffffffffu, tm1, 1));
        tm1 = fmaxf(tm1, __shfl_xor_sync(0xffffffffu, tm1, 2));

        float mn0 = fmaxf(m0, tm0), mn1 = fmaxf(m1, tm1);
        float f0 = __expf(m0 - mn0), f1 = __expf(m1 - mn1);
        float rs0 = 0.f, rs1 = 0.f;
#pragma unroll
        for (int nt = 0; nt < 8; nt++) {
            s[nt][0] = __expf(s[nt][0] - mn0);
            s[nt][1] = __expf(s[nt][1] - mn0);
            s[nt][2] = __expf(s[nt][2] - mn1);
            s[nt][3] = __expf(s[nt][3] - mn1);
            rs0 += s[nt][0] + s[nt][1];
            rs1 += s[nt][2] + s[nt][3];
        }
        rs0 += __shfl_xor_sync(0xffffffffu, rs0, 1);
        rs0 += __shfl_xor_sync(0xffffffffu, rs0, 2);
        rs1 += __shfl_xor_sync(0xffffffffu, rs1, 1);
        rs1 += __shfl_xor_sync(0xffffffffu, rs1, 2);
        l0 = l0 * f0 + rs0;  m0 = mn0;
        l1 = l1 * f1 + rs1;  m1 = mn1;
#pragma unroll
        for (int nt = 0; nt < 8; nt++) {
            o[nt][0] *= f0; o[nt][1] *= f0;
            o[nt][2] *= f1; o[nt][3] *= f1;
        }

#pragma unroll
        for (int nt = 0; nt < 8; nt++) {
            uint2 p0 = {f2tf(s[nt][0]), f2tf(s[nt][1])};
            uint2 p1 = {f2tf(s[nt][2]), f2tf(s[nt][3])};
            *(uint2*)&Ps[(row_w + gID) * SPAD + nt * 8 + 2 * tig] = p0;
            *(uint2*)&Ps[(row_w + gID + 8) * SPAD + nt * 8 + 2 * tig] = p1;
        }
        __syncthreads();

#pragma unroll
        for (int ks = 0; ks < 8; ks++) {
            unsigned a0 = Ps[(row_w + gID) * SPAD + ks * 8 + tig];
            unsigned a1 = Ps[(row_w + gID + 8) * SPAD + ks * 8 + tig];
            unsigned a2 = Ps[(row_w + gID) * SPAD + ks * 8 + tig + 4];
            unsigned a3 = Ps[(row_w + gID + 8) * SPAD + ks * 8 + tig + 4];
#pragma unroll
            for (int nt = 0; nt < 8; nt++) {
                unsigned b0 = Vs[(ks * 8 + tig) * SPAD + nt * 8 + gID];
                unsigned b1 = Vs[(ks * 8 + tig + 4) * SPAD + nt * 8 + gID];
                MMA_TF32(o[nt], a0, a1, a2, a3, b0, b1);
            }
        }
    }

    // epilogue: tf32-rounded attn_v so proj GEMM truncation is exact RNA
    float invl0 = 1.f / l0, invl1 = 1.f / l1;
    float* op0 = att_out + ((size_t)b * Tt + r0g) * Cc + h * Dd;
    float* op1 = att_out + ((size_t)b * Tt + r1g) * Cc + h * Dd;
#pragma unroll
    for (int nt = 0; nt < 8; nt++) {
        int c = nt * 8 + 2 * tig;
        float2 v0 = {__uint_as_float(f2tf(o[nt][0] * invl0)),
                     __uint_as_float(f2tf(o[nt][1] * invl0))};
        float2 v1 = {__uint_as_float(f2tf(o[nt][2] * invl1)),
                     __uint_as_float(f2tf(o[nt][3] * invl1))};
        *(float2*)(op0 + c) = v0;
        *(float2*)(op1 + c) = v1;
    }
    if (tig == 0) {
        size_t row = (size_t)(b * Hh + h) * Tt + r0g;
        ml[row * 2] = m0;  ml[row * 2 + 1] = l0;
        ml[(row + 8) * 2] = m1;  ml[(row + 8) * 2 + 1] = l1;
    }
}

// ---------------------------------------------------------------------------
// Normalization: read only causal region; zeros elsewhere. HBM-roofline bound.
// ---------------------------------------------------------------------------
__global__ __launch_bounds__(256) void attn_norm_kernel(
    float* __restrict__ attn_w, const float* __restrict__ ml)
{
    const int row = blockIdx.x;
    const int q = row & (Tt - 1);
    const float mrow = ml[(size_t)row * 2];
    const float invl = 1.f / ml[(size_t)row * 2 + 1];
    float* base = attn_w + (size_t)row * Tt;

    for (int c0 = threadIdx.x * 4; c0 < Tt; c0 += 256 * 4) {
        if (c0 > q) {
            float4 z = {0.f, 0.f, 0.f, 0.f};
            *(float4*)(base + c0) = z;
        } else {
            float4 s = *(const float4*)(base + c0);
            float4 w;
            w.x = (c0 + 0 > q) ? 0.f : __expf(s.x - mrow) * invl;
            w.y = (c0 + 1 > q) ? 0.f : __expf(s.y - mrow) * invl;
            w.z = (c0 + 2 > q) ? 0.f : __expf(s.z - mrow) * invl;
            w.w = (c0 + 3 > q) ? 0.f : __expf(s.w - mrow) * invl;
            *(float4*)(base + c0) = w;
        }
    }
}

// ---------------------------------------------------------------------------
extern "C" void kernel_launch(void* const* d_in, const int* in_sizes, int n_in,
                              void* d_out, int out_size)
{
    const float* x     = (const float*)d_in[0];
    const float* w_qkv = (const float*)d_in[1];
    const float* b_qkv = (const float*)d_in[2];
    const float* w_o   = (const float*)d_in[3];
    const float* b_o   = (const float*)d_in[4];
    float* out = (float*)d_out;

    float *qkv_ptr, *att_ptr, *ml_ptr, *x_ptr, *wqkv_ptr, *wo_ptr;
    cudaGetSymbolAddress((void**)&qkv_ptr, g_qkv);
    cudaGetSymbolAddress((void**)&att_ptr, g_att);
    cudaGetSymbolAddress((void**)&ml_ptr, g_ml);
    cudaGetSymbolAddress((void**)&x_ptr, g_x);
    cudaGetSymbolAddress((void**)&wqkv_ptr, g_wqkv);
    cudaGetSymbolAddress((void**)&wo_ptr, g_wo);

    const size_t o_elems    = (size_t)Bb * Tt * Cc;
    const size_t attn_elems = (size_t)Bb * Hh * Tt * (size_t)Tt;
    int write_attn = ((size_t)out_size >= o_elems + attn_elems) ? 1 : 0;
    float* attn_w_ptr = write_attn ? (out + o_elems) : nullptr;

    const int attn_smem = (128 + 64 + 64 + 128) * SPAD * sizeof(unsigned);
    cudaFuncSetAttribute(attn_tc_kernel,
                         cudaFuncAttributeMaxDynamicSharedMemorySize, attn_smem);

    // 0) pre-round operands to tf32-exact fp32 (RNA)
    {
        int nx = BT * Cc, nw1 = Cc * C3, nw2 = Cc * Cc;
        round_tf32_kernel<<<nx / 1024, 256>>>(x, x_ptr, nx);
        round_tf32_kernel<<<nw1 / 1024, 256>>>(w_qkv, wqkv_ptr, nw1);
        round_tf32_kernel<<<nw2 / 1024, 256>>>(w_o, wo_ptr, nw2);
    }
    // 1) QKV projection
    {
        dim3 grid(C3 / 128, BT / 128);
        gemm_tc_kernel<<<grid, 256>>>(x_ptr, wqkv_ptr, b_qkv, qkv_ptr, BT, C3, Cc);
    }
    // 2) causal attention (raw scores + m,l + attn_v)
    {
        dim3 grid(Tt / 128, Hh, Bb);
        attn_tc_kernel<<<grid, 256, attn_smem>>>(qkv_ptr, attn_w_ptr, att_ptr,
                                                 ml_ptr, write_attn);
    }
    // 3) normalize attn_w
    if (write_attn) {
        attn_norm_kernel<<<Bb * Hh * Tt, 256>>>(attn_w_ptr, ml_ptr);
    }
    // 4) output projection
    {
        dim3 grid(Cc / 128, BT / 128);
        gemm_tc_kernel<<<grid, 256>>>(att_ptr, wo_ptr, b_o, out, BT, Cc, Cc);
    }
}

// round 13
// speedup vs baseline: 1.3839x; 1.1153x over previous
#include <cuda_runtime.h>
#include <math.h>

#define Bb 2
#define Tt 2048
#define Cc 1024
#define Hh 16
#define Dd 64
#define BT (Bb*Tt)      // 4096
#define C3 (3*Cc)       // 3072

#define QSTR 68   // Qs/Ps row stride (words): A-frag bank = 4*gID+tig, conflict-free
#define KSTR 68   // Ks row stride: S-mma B-frag bank = 4*gID(+..), conflict-free
#define VSTR 72   // Vs row stride: PV B-frag bank = 8*tig+gID, conflict-free

// Scratch (allocation-free rule: __device__ globals)
__device__ float g_qkv[(size_t)BT * C3];           // [B,T,3C] tf32-exact values
__device__ float g_att[(size_t)BT * Cc];           // attn_v (tf32-exact values)
__device__ float g_ml[(size_t)Bb * Hh * Tt * 2];   // per-row (m,l)
__device__ float g_x[(size_t)BT * Cc];             // tf32-rounded x
__device__ float g_wqkv[(size_t)Cc * C3];          // tf32-rounded w_qkv
__device__ float g_wo[(size_t)Cc * Cc];            // tf32-rounded w_o

__device__ __forceinline__ unsigned f2tf(float x) {
    unsigned r;
    asm("cvt.rna.tf32.f32 %0, %1;" : "=r"(r) : "f"(x));
    return r;
}

__device__ __forceinline__ void cp16(void* dst, const void* src) {
    unsigned d = (unsigned)__cvta_generic_to_shared(dst);
    asm volatile("cp.async.cg.shared.global [%0], [%1], 16;" :: "r"(d), "l"(src));
}
#define CP_COMMIT() asm volatile("cp.async.commit_group;")
#define CP_WAIT2()  asm volatile("cp.async.wait_group 2;")
#define CP_WAIT0()  asm volatile("cp.async.wait_group 0;")

#define MMA_TF32(c, a0,a1,a2,a3, b0,b1)                                   \
    asm volatile(                                                          \
        "mma.sync.aligned.m16n8k8.row.col.f32.tf32.tf32.f32 "             \
        "{%0,%1,%2,%3}, {%4,%5,%6,%7}, {%8,%9}, {%0,%1,%2,%3};"           \
        : "+f"((c)[0]), "+f"((c)[1]), "+f"((c)[2]), "+f"((c)[3])          \
        : "r"(a0), "r"(a1), "r"(a2), "r"(a3), "r"(b0), "r"(b1))

// ---------------------------------------------------------------------------
__global__ __launch_bounds__(256) void round_tf32_kernel(
    const float* __restrict__ in, float* __restrict__ outp, int n)
{
    int i = (blockIdx.x * 256 + threadIdx.x) * 4;
    if (i < n) {
        float4 v = *(const float4*)(in + i);
        v.x = __uint_as_float(f2tf(v.x));
        v.y = __uint_as_float(f2tf(v.y));
        v.z = __uint_as_float(f2tf(v.z));
        v.w = __uint_as_float(f2tf(v.w));
        *(float4*)(outp + i) = v;
    }
}

// ---------------------------------------------------------------------------
// TF32 tensor-core GEMM, 4-stage cp.async, conflict-free smem strides.
// Operands must be tf32-exact fp32. If round_out, output = tf32(acc + bias).
// BM=BN=128, BK=16, 8 warps. As stride 20, Bs stride 136.
// ---------------------------------------------------------------------------
#define AS_STRIDE 20
#define BS_STRIDE 136
#define AS_TILE (128 * AS_STRIDE)    // 2560 words
#define BS_TILE (16 * BS_STRIDE)     // 2176 words
#define GEMM_SMEM_W (4 * (AS_TILE + BS_TILE))  // 18944 words = 75776 B

__global__ __launch_bounds__(256) void gemm_tc_kernel(
    const float* __restrict__ A, const float* __restrict__ W,
    const float* __restrict__ bias, float* __restrict__ out,
    int M, int N, int K, int round_out)
{
    extern __shared__ float gsm[];
    float* Asm = gsm;                       // [4][128][AS_STRIDE]
    float* Bsm = gsm + 4 * AS_TILE;         // [4][16][BS_STRIDE]

    const int tid  = threadIdx.x;
    const int warp = tid >> 5, lane = tid & 31;
    const int gID  = lane >> 2, tig = lane & 3;
    const int wm = (warp >> 2) * 64;
    const int wn = (warp & 3) * 32;
    const int row0 = blockIdx.y * 128;
    const int col0 = blockIdx.x * 128;

    const int aR = tid >> 2;
    const int aK = (tid & 3) * 4;
    const int bK = tid >> 4;
    const int bN = (tid & 15) * 8;

    const float* Ap  = A + (size_t)(row0 + aR) * K + aK;
    const float* Ap2 = Ap + (size_t)64 * K;
    const float* Wp  = W + (size_t)bK * N + col0 + bN;

    float acc[4][4][4];
#pragma unroll
    for (int mt = 0; mt < 4; mt++)
#pragma unroll
        for (int nt = 0; nt < 4; nt++)
#pragma unroll
            for (int i = 0; i < 4; i++) acc[mt][nt][i] = 0.f;

    const int ntile = K / 16;

    // prologue: stages 0..2
#pragma unroll
    for (int p = 0; p < 3; p++) {
        int k0 = p * 16;
        float* As = Asm + p * AS_TILE;
        float* Bs = Bsm + p * BS_TILE;
        cp16(As + aR * AS_STRIDE + aK, Ap + k0);
        cp16(As + (aR + 64) * AS_STRIDE + aK, Ap2 + k0);
        cp16(Bs + bK * BS_STRIDE + bN, Wp + (size_t)k0 * N);
        cp16(Bs + bK * BS_STRIDE + bN + 4, Wp + (size_t)k0 * N + 4);
        CP_COMMIT();
    }

    int buf = 0;
    for (int t = 0; t < ntile; t++) {
        CP_WAIT2();
        __syncthreads();

        if (t + 3 < ntile) {
            int slot = (buf + 3) & 3;
            int k0 = (t + 3) * 16;
            float* As = Asm + slot * AS_TILE;
            float* Bs = Bsm + slot * BS_TILE;
            cp16(As + aR * AS_STRIDE + aK, Ap + k0);
            cp16(As + (aR + 64) * AS_STRIDE + aK, Ap2 + k0);
            cp16(Bs + bK * BS_STRIDE + bN, Wp + (size_t)k0 * N);
            cp16(Bs + bK * BS_STRIDE + bN + 4, Wp + (size_t)k0 * N + 4);
        }
        CP_COMMIT();

        const float* As = Asm + buf * AS_TILE;
        const float* Bs = Bsm + buf * BS_TILE;
#pragma unroll
        for (int ks = 0; ks < 16; ks += 8) {
            unsigned af[4][4], bf[4][2];
#pragma unroll
            for (int mt = 0; mt < 4; mt++) {
                int r = wm + mt * 16 + gID;
                af[mt][0] = __float_as_uint(As[r * AS_STRIDE + ks + tig]);
                af[mt][1] = __float_as_uint(As[(r + 8) * AS_STRIDE + ks + tig]);
                af[mt][2] = __float_as_uint(As[r * AS_STRIDE + ks + tig + 4]);
                af[mt][3] = __float_as_uint(As[(r + 8) * AS_STRIDE + ks + tig + 4]);
            }
#pragma unroll
            for (int nt = 0; nt < 4; nt++) {
                int c = wn + nt * 8 + gID;
                bf[nt][0] = __float_as_uint(Bs[(ks + tig) * BS_STRIDE + c]);
                bf[nt][1] = __float_as_uint(Bs[(ks + tig + 4) * BS_STRIDE + c]);
            }
#pragma unroll
            for (int mt = 0; mt < 4; mt++)
#pragma unroll
                for (int nt = 0; nt < 4; nt++)
                    MMA_TF32(acc[mt][nt], af[mt][0], af[mt][1], af[mt][2], af[mt][3],
                             bf[nt][0], bf[nt][1]);
        }
        buf = (buf + 1) & 3;
    }

#pragma unroll
    for (int mt = 0; mt < 4; mt++) {
        int r = row0 + wm + mt * 16 + gID;
#pragma unroll
        for (int nt = 0; nt < 4; nt++) {
            int c = col0 + wn + nt * 8 + 2 * tig;
            float b0v = bias[c], b1v = bias[c + 1];
            float2 v0 = {acc[mt][nt][0] + b0v, acc[mt][nt][1] + b1v};
            float2 v1 = {acc[mt][nt][2] + b0v, acc[mt][nt][3] + b1v};
            if (round_out) {
                v0.x = __uint_as_float(f2tf(v0.x));
                v0.y = __uint_as_float(f2tf(v0.y));
                v1.x = __uint_as_float(f2tf(v1.x));
                v1.y = __uint_as_float(f2tf(v1.y));
            }
            *(float2*)(out + (size_t)r * N + c) = v0;
            *(float2*)(out + (size_t)(r + 8) * N + c) = v1;
        }
    }
}

// ---------------------------------------------------------------------------
// TF32 tensor-core flash attention. qkv holds tf32-exact values, so K/V are
// cp.async'd raw (no conversion, no staging). Block = (b,h,128 q-rows), 8 warps.
// ---------------------------------------------------------------------------
__global__ __launch_bounds__(256) void attn_tc_kernel(
    const float* __restrict__ qkv,
    float* __restrict__ attn_w,
    float* __restrict__ att_out,
    float* __restrict__ ml,
    int write_attn)
{
    extern __shared__ unsigned smu[];
    unsigned* Qs = smu;                      // [128][QSTR]
    unsigned* Ks = Qs + 128 * QSTR;          // [64][KSTR]
    unsigned* Vs = Ks + 64 * KSTR;           // [64][VSTR]
    unsigned* Ps = Vs + 64 * VSTR;           // [128][QSTR]

    const int tid  = threadIdx.x;
    const int warp = tid >> 5, lane = tid & 31;
    const int gID  = lane >> 2, tig = lane & 3;
    const int qt = (Tt / 128 - 1) - blockIdx.x;
    const int h  = blockIdx.y;
    const int b  = blockIdx.z;
    const int q0 = qt * 128;
    const int row_w = warp * 16;

    const float* Qg = qkv + ((size_t)b * Tt + q0) * C3 + h * Dd;
    const float* Kg = qkv + (size_t)b * Tt * C3 + Cc + h * Dd;
    const float* Vg = qkv + (size_t)b * Tt * C3 + 2 * Cc + h * Dd;

    // Q: already tf32-exact; *0.125 is exact
    for (int idx = tid; idx < 2048; idx += 256) {
        int q = idx >> 4, dc = (idx & 15) << 2;
        float4 v = *(const float4*)(Qg + (size_t)q * C3 + dc);
        unsigned* p = Qs + q * QSTR + dc;
        p[0] = __float_as_uint(v.x * 0.125f);
        p[1] = __float_as_uint(v.y * 0.125f);
        p[2] = __float_as_uint(v.z * 0.125f);
        p[3] = __float_as_uint(v.w * 0.125f);
    }

    float m0 = -1e30f, m1 = -1e30f, l0 = 0.f, l1 = 0.f;
    float o[8][4];
#pragma unroll
    for (int nt = 0; nt < 8; nt++)
#pragma unroll
        for (int i = 0; i < 4; i++) o[nt][i] = 0.f;

    const int r0g = q0 + row_w + gID;
    const int r1g = r0g + 8;
    const size_t wrow0 = ((size_t)(b * Hh + h) * Tt + r0g) * (size_t)Tt;
    const size_t wrow1 = wrow0 + 8 * (size_t)Tt;

    const int nkt = 2 * qt + 2;
    for (int kt = 0; kt < nkt; kt++) {
        const int j0 = kt * 64;
        __syncthreads();   // previous-tile consumers done before overwrite
        // cp.async K and V tiles (raw tf32-exact floats)
        for (int idx = tid; idx < 1024; idx += 256) {
            int j = idx >> 4, dc = (idx & 15) << 2;
            cp16(Ks + j * KSTR + dc, Kg + (size_t)(j0 + j) * C3 + dc);
            cp16(Vs + j * VSTR + dc, Vg + (size_t)(j0 + j) * C3 + dc);
        }
        CP_COMMIT();
        CP_WAIT0();
        __syncthreads();

        float s[8][4];
#pragma unroll
        for (int nt = 0; nt < 8; nt++)
#pragma unroll
            for (int i = 0; i < 4; i++) s[nt][i] = 0.f;
#pragma unroll
        for (int ks = 0; ks < 8; ks++) {
            unsigned a0 = Qs[(row_w + gID) * QSTR + ks * 8 + tig];
            unsigned a1 = Qs[(row_w + gID + 8) * QSTR + ks * 8 + tig];
            unsigned a2 = Qs[(row_w + gID) * QSTR + ks * 8 + tig + 4];
            unsigned a3 = Qs[(row_w + gID + 8) * QSTR + ks * 8 + tig + 4];
#pragma unroll
            for (int nt = 0; nt < 8; nt++) {
                unsigned b0 = Ks[(nt * 8 + gID) * KSTR + ks * 8 + tig];
                unsigned b1 = Ks[(nt * 8 + gID) * KSTR + ks * 8 + tig + 4];
                MMA_TF32(s[nt], a0, a1, a2, a3, b0, b1);
            }
        }

        if (kt >= 2 * qt) {
#pragma unroll
            for (int nt = 0; nt < 8; nt++) {
                int c = j0 + nt * 8 + 2 * tig;
                if (c     > r0g) s[nt][0] = -1e30f;
                if (c + 1 > r0g) s[nt][1] = -1e30f;
                if (c     > r1g) s[nt][2] = -1e30f;
                if (c + 1 > r1g) s[nt][3] = -1e30f;
            }
        }

        if (write_attn) {
#pragma unroll
            for (int nt = 0; nt < 8; nt++) {
                int c = j0 + nt * 8 + 2 * tig;
                float2 v0 = {s[nt][0], s[nt][1]};
                float2 v1 = {s[nt][2], s[nt][3]};
                *(float2*)(attn_w + wrow0 + c) = v0;
                *(float2*)(attn_w + wrow1 + c) = v1;
            }
        }

        float tm0 = -1e30f, tm1 = -1e30f;
#pragma unroll
        for (int nt = 0; nt < 8; nt++) {
            tm0 = fmaxf(tm0, fmaxf(s[nt][0], s[nt][1]));
            tm1 = fmaxf(tm1, fmaxf(s[nt][2], s[nt][3]));
        }
        tm0 = fmaxf(tm0, __shfl_xor_sync(0xffffffffu, tm0, 1));
        tm0 = fmaxf(tm0, __shfl_xor_sync(0xffffffffu, tm0, 2));
        tm1 = fmaxf(tm1, __shfl_xor_sync(0xffffffffu, tm1, 1));
        tm1 = fmaxf(tm1, __shfl_xor_sync(0xffffffffu, tm1, 2));

        float mn0 = fmaxf(m0, tm0), mn1 = fmaxf(m1, tm1);
        float f0 = __expf(m0 - mn0), f1 = __expf(m1 - mn1);
        float rs0 = 0.f, rs1 = 0.f;
#pragma unroll
        for (int nt = 0; nt < 8; nt++) {
            s[nt][0] = __expf(s[nt][0] - mn0);
            s[nt][1] = __expf(s[nt][1] - mn0);
            s[nt][2] = __expf(s[nt][2] - mn1);
            s[nt][3] = __expf(s[nt][3] - mn1);
            rs0 += s[nt][0] + s[nt][1];
            rs1 += s[nt][2] + s[nt][3];
        }
        rs0 += __shfl_xor_sync(0xffffffffu, rs0, 1);
        rs0 += __shfl_xor_sync(0xffffffffu, rs0, 2);
        rs1 += __shfl_xor_sync(0xffffffffu, rs1, 1);
        rs1 += __shfl_xor_sync(0xffffffffu, rs1, 2);
        l0 = l0 * f0 + rs0;  m0 = mn0;
        l1 = l1 * f1 + rs1;  m1 = mn1;
#pragma unroll
        for (int nt = 0; nt < 8; nt++) {
            o[nt][0] *= f0; o[nt][1] *= f0;
            o[nt][2] *= f1; o[nt][3] *= f1;
        }

#pragma unroll
        for (int nt = 0; nt < 8; nt++) {
            uint2 p0 = {f2tf(s[nt][0]), f2tf(s[nt][1])};
            uint2 p1 = {f2tf(s[nt][2]), f2tf(s[nt][3])};
            *(uint2*)&Ps[(row_w + gID) * QSTR + nt * 8 + 2 * tig] = p0;
            *(uint2*)&Ps[(row_w + gID + 8) * QSTR + nt * 8 + 2 * tig] = p1;
        }
        __syncthreads();

#pragma unroll
        for (int ks = 0; ks < 8; ks++) {
            unsigned a0 = Ps[(row_w + gID) * QSTR + ks * 8 + tig];
            unsigned a1 = Ps[(row_w + gID + 8) * QSTR + ks * 8 + tig];
            unsigned a2 = Ps[(row_w + gID) * QSTR + ks * 8 + tig + 4];
            unsigned a3 = Ps[(row_w + gID + 8) * QSTR + ks * 8 + tig + 4];
#pragma unroll
            for (int nt = 0; nt < 8; nt++) {
                unsigned b0 = Vs[(ks * 8 + tig) * VSTR + nt * 8 + gID];
                unsigned b1 = Vs[(ks * 8 + tig + 4) * VSTR + nt * 8 + gID];
                MMA_TF32(o[nt], a0, a1, a2, a3, b0, b1);
            }
        }
    }

    // epilogue: tf32-exact attn_v so proj GEMM truncation is exact RNA
    float invl0 = 1.f / l0, invl1 = 1.f / l1;
    float* op0 = att_out + ((size_t)b * Tt + r0g) * Cc + h * Dd;
    float* op1 = att_out + ((size_t)b * Tt + r1g) * Cc + h * Dd;
#pragma unroll
    for (int nt = 0; nt < 8; nt++) {
        int c = nt * 8 + 2 * tig;
        float2 v0 = {__uint_as_float(f2tf(o[nt][0] * invl0)),
                     __uint_as_float(f2tf(o[nt][1] * invl0))};
        float2 v1 = {__uint_as_float(f2tf(o[nt][2] * invl1)),
                     __uint_as_float(f2tf(o[nt][3] * invl1))};
        *(float2*)(op0 + c) = v0;
        *(float2*)(op1 + c) = v1;
    }
    if (tig == 0) {
        size_t row = (size_t)(b * Hh + h) * Tt + r0g;
        ml[row * 2] = m0;  ml[row * 2 + 1] = l0;
        ml[(row + 8) * 2] = m1;  ml[(row + 8) * 2 + 1] = l1;
    }
}

// ---------------------------------------------------------------------------
__global__ __launch_bounds__(256) void attn_norm_kernel(
    float* __restrict__ attn_w, const float* __restrict__ ml)
{
    const int row = blockIdx.x;
    const int q = row & (Tt - 1);
    const float mrow = ml[(size_t)row * 2];
    const float invl = 1.f / ml[(size_t)row * 2 + 1];
    float* base = attn_w + (size_t)row * Tt;

    for (int c0 = threadIdx.x * 4; c0 < Tt; c0 += 256 * 4) {
        if (c0 > q) {
            float4 z = {0.f, 0.f, 0.f, 0.f};
            *(float4*)(base + c0) = z;
        } else {
            float4 s = *(const float4*)(base + c0);
            float4 w;
            w.x = (c0 + 0 > q) ? 0.f : __expf(s.x - mrow) * invl;
            w.y = (c0 + 1 > q) ? 0.f : __expf(s.y - mrow) * invl;
            w.z = (c0 + 2 > q) ? 0.f : __expf(s.z - mrow) * invl;
            w.w = (c0 + 3 > q) ? 0.f : __expf(s.w - mrow) * invl;
            *(float4*)(base + c0) = w;
        }
    }
}

// ---------------------------------------------------------------------------
extern "C" void kernel_launch(void* const* d_in, const int* in_sizes, int n_in,
                              void* d_out, int out_size)
{
    const float* x     = (const float*)d_in[0];
    const float* w_qkv = (const float*)d_in[1];
    const float* b_qkv = (const float*)d_in[2];
    const float* w_o   = (const float*)d_in[3];
    const float* b_o   = (const float*)d_in[4];
    float* out = (float*)d_out;

    float *qkv_ptr, *att_ptr, *ml_ptr, *x_ptr, *wqkv_ptr, *wo_ptr;
    cudaGetSymbolAddress((void**)&qkv_ptr, g_qkv);
    cudaGetSymbolAddress((void**)&att_ptr, g_att);
    cudaGetSymbolAddress((void**)&ml_ptr, g_ml);
    cudaGetSymbolAddress((void**)&x_ptr, g_x);
    cudaGetSymbolAddress((void**)&wqkv_ptr, g_wqkv);
    cudaGetSymbolAddress((void**)&wo_ptr, g_wo);

    const size_t o_elems    = (size_t)Bb * Tt * Cc;
    const size_t attn_elems = (size_t)Bb * Hh * Tt * (size_t)Tt;
    int write_attn = ((size_t)out_size >= o_elems + attn_elems) ? 1 : 0;
    float* attn_w_ptr = write_attn ? (out + o_elems) : nullptr;

    const int gemm_smem = GEMM_SMEM_W * sizeof(float);                  // 75776
    const int attn_smem = (128 * QSTR + 64 * KSTR + 64 * VSTR + 128 * QSTR)
                          * sizeof(unsigned);                            // 105472
    cudaFuncSetAttribute(gemm_tc_kernel,
                         cudaFuncAttributeMaxDynamicSharedMemorySize, gemm_smem);
    cudaFuncSetAttribute(attn_tc_kernel,
                         cudaFuncAttributeMaxDynamicSharedMemorySize, attn_smem);

    // 0) pre-round operands to tf32-exact fp32 (RNA)
    {
        int nx = BT * Cc, nw1 = Cc * C3, nw2 = Cc * Cc;
        round_tf32_kernel<<<nx / 1024, 256>>>(x, x_ptr, nx);
        round_tf32_kernel<<<nw1 / 1024, 256>>>(w_qkv, wqkv_ptr, nw1);
        round_tf32_kernel<<<nw2 / 1024, 256>>>(w_o, wo_ptr, nw2);
    }
    // 1) QKV projection; output rounded to tf32-exact for the attention stage
    {
        dim3 grid(C3 / 128, BT / 128);
        gemm_tc_kernel<<<grid, 256, gemm_smem>>>(x_ptr, wqkv_ptr, b_qkv, qkv_ptr,
                                                 BT, C3, Cc, 1);
    }
    // 2) causal attention (raw scores + m,l + attn_v)
    {
        dim3 grid(Tt / 128, Hh, Bb);
        attn_tc_kernel<<<grid, 256, attn_smem>>>(qkv_ptr, attn_w_ptr, att_ptr,
                                                 ml_ptr, write_attn);
    }
    // 3) normalize attn_w
    if (write_attn) {
        attn_norm_kernel<<<Bb * Hh * Tt, 256>>>(attn_w_ptr, ml_ptr);
    }
    // 4) output projection
    {
        dim3 grid(Cc / 128, BT / 128);
        gemm_tc_kernel<<<grid, 256, gemm_smem>>>(att_ptr, wo_ptr, b_o, out,
                                                 BT, Cc, Cc, 0);
    }
}

// round 15
// speedup vs baseline: 1.5210x; 1.0991x over previous
#include <cuda_runtime.h>
#include <math.h>

#define Bb 2
#define Tt 2048
#define Cc 1024
#define Hh 16
#define Dd 64
#define BT (Bb*Tt)      // 4096
#define C3 (3*Cc)       // 3072

#define QSTR 72   // attention smem strides (words) — bank-conflict-free for uint2 frags
#define KSTR 72
#define VSTR 72

// Scratch (allocation-free rule: __device__ globals)
__device__ float g_qkv[(size_t)BT * C3];           // [B,T,3C] tf32-exact, d-perm8
__device__ float g_att[(size_t)BT * Cc];           // attn_v tf32-exact, d-perm8
__device__ float g_ml[(size_t)Bb * Hh * Tt * 2];   // per-row (m,l)
__device__ float g_x[(size_t)BT * Cc];             // x: tf32-rounded, k-perm8
__device__ float g_wqkv[(size_t)Cc * C3];          // w_qkv^T [3C][C]: rounded, k-perm8
__device__ float g_wo[(size_t)Cc * Cc];            // w_o^T   [C][C]:  rounded, k-perm8

__device__ __forceinline__ unsigned f2tf(float x) {
    unsigned r;
    asm("cvt.rna.tf32.f32 %0, %1;" : "=r"(r) : "f"(x));
    return r;
}

__device__ __forceinline__ void cp16(void* dst, const void* src) {
    unsigned d = (unsigned)__cvta_generic_to_shared(dst);
    asm volatile("cp.async.cg.shared.global [%0], [%1], 16;" :: "r"(d), "l"(src));
}
#define CP_COMMIT() asm volatile("cp.async.commit_group;")
#define CP_WAIT2()  asm volatile("cp.async.wait_group 2;")
#define CP_WAIT0()  asm volatile("cp.async.wait_group 0;")

#define MMA_TF32(c, a0,a1,a2,a3, b0,b1)                                   \
    asm volatile(                                                          \
        "mma.sync.aligned.m16n8k8.row.col.f32.tf32.tf32.f32 "             \
        "{%0,%1,%2,%3}, {%4,%5,%6,%7}, {%8,%9}, {%0,%1,%2,%3};"           \
        : "+f"((c)[0]), "+f"((c)[1]), "+f"((c)[2]), "+f"((c)[3])          \
        : "r"(a0), "r"(a1), "r"(a2), "r"(a3), "r"(b0), "r"(b1))

// ---------------------------------------------------------------------------
// prep: round to tf32-exact + perm8 the k layout (pairs (k,k+4) adjacent)
// ---------------------------------------------------------------------------
__global__ __launch_bounds__(256) void prep_x_kernel(
    const float* __restrict__ in, float* __restrict__ outp, int n)
{
    int i = (blockIdx.x * 256 + threadIdx.x) * 4;
    if (i < n) {
        float4 v = *(const float4*)(in + i);
        // i % 4 == 0; group of 4 maps to stride-2 positions starting at pbase
        int pbase = (i & ~7) + ((i & 4) >> 2);
        outp[pbase + 0] = __uint_as_float(f2tf(v.x));
        outp[pbase + 2] = __uint_as_float(f2tf(v.y));
        outp[pbase + 4] = __uint_as_float(f2tf(v.z));
        outp[pbase + 6] = __uint_as_float(f2tf(v.w));
    }
}

// W[K][N] -> Wt[N][K] with perm8 on k, rounded. 32x32 tiles, block (32,8).
__global__ __launch_bounds__(256) void prep_wt_kernel(
    const float* __restrict__ W, float* __restrict__ Wt, int K, int N)
{
    __shared__ float tile[32][33];
    int k0 = blockIdx.y * 32, n0 = blockIdx.x * 32;
    int tx = threadIdx.x, ty = threadIdx.y;
#pragma unroll
    for (int i = 0; i < 4; i++)
        tile[ty + i * 8][tx] = W[(size_t)(k0 + ty + i * 8) * N + n0 + tx];
    __syncthreads();
    int kp = (tx & ~7) | ((tx & 3) << 1) | ((tx & 4) >> 2);
#pragma unroll
    for (int i = 0; i < 4; i++) {
        int n = n0 + ty + i * 8;
        Wt[(size_t)n * K + k0 + kp] = __uint_as_float(f2tf(tile[tx][ty + i * 8]));
    }
}

// ---------------------------------------------------------------------------
// TF32 GEMM, 4-stage cp.async, ALL fragment loads are uint2 (perm8 layout).
// A[M][K] perm8, Wt[N][K] perm8 (pre-transposed). out = A @ Wt^T + bias.
// perm_round_out: write output columns perm8'd + tf32-rounded (for qkv).
// ---------------------------------------------------------------------------
#define AST 24
#define GT_WORDS (128 * AST)                 // 3072 words per operand tile
#define GEMM_SMEM_W (4 * 2 * GT_WORDS)       // 24576 words = 98304 B

__global__ __launch_bounds__(256) void gemm_tc_kernel(
    const float* __restrict__ A, const float* __restrict__ Wt,
    const float* __restrict__ bias, float* __restrict__ out,
    int M, int N, int K, int perm_round_out)
{
    extern __shared__ float gsm[];

    const int tid  = threadIdx.x;
    const int warp = tid >> 5, lane = tid & 31;
    const int gID  = lane >> 2, tig = lane & 3;
    const int wm = (warp >> 2) * 64;
    const int wn = (warp & 3) * 32;
    const int row0 = blockIdx.y * 128;
    const int col0 = blockIdx.x * 128;

    const int aR = tid >> 2;              // 0..63
    const int aK = (tid & 3) * 4;

    const float* Ap  = A  + (size_t)(row0 + aR) * K + aK;
    const float* Ap2 = Ap + (size_t)64 * K;
    const float* Bp  = Wt + (size_t)(col0 + aR) * K + aK;
    const float* Bp2 = Bp + (size_t)64 * K;

    float acc[4][4][4];
#pragma unroll
    for (int mt = 0; mt < 4; mt++)
#pragma unroll
        for (int nt = 0; nt < 4; nt++)
#pragma unroll
            for (int i = 0; i < 4; i++) acc[mt][nt][i] = 0.f;

    const int ntile = K / 16;

#pragma unroll
    for (int p = 0; p < 3; p++) {
        int k0 = p * 16;
        float* As = gsm + p * 2 * GT_WORDS;
        float* Bs = As + GT_WORDS;
        cp16(As + aR * AST + aK, Ap + k0);
        cp16(As + (aR + 64) * AST + aK, Ap2 + k0);
        cp16(Bs + aR * AST + aK, Bp + k0);
        cp16(Bs + (aR + 64) * AST + aK, Bp2 + k0);
        CP_COMMIT();
    }

    int buf = 0;
    for (int t = 0; t < ntile; t++) {
        CP_WAIT2();
        __syncthreads();

        if (t + 3 < ntile) {
            int slot = (buf + 3) & 3;
            int k0 = (t + 3) * 16;
            float* As = gsm + slot * 2 * GT_WORDS;
            float* Bs = As + GT_WORDS;
            cp16(As + aR * AST + aK, Ap + k0);
            cp16(As + (aR + 64) * AST + aK, Ap2 + k0);
            cp16(Bs + aR * AST + aK, Bp + k0);
            cp16(Bs + (aR + 64) * AST + aK, Bp2 + k0);
        }
        CP_COMMIT();

        const float* As = gsm + buf * 2 * GT_WORDS;
        const float* Bs = As + GT_WORDS;
#pragma unroll
        for (int ks = 0; ks < 16; ks += 8) {
            unsigned af[4][4], bf[4][2];
#pragma unroll
            for (int mt = 0; mt < 4; mt++) {
                int r = wm + mt * 16 + gID;
                uint2 lo = *(const uint2*)&As[r * AST + ks + 2 * tig];
                uint2 hi = *(const uint2*)&As[(r + 8) * AST + ks + 2 * tig];
                af[mt][0] = lo.x; af[mt][1] = hi.x;
                af[mt][2] = lo.y; af[mt][3] = hi.y;
            }
#pragma unroll
            for (int nt = 0; nt < 4; nt++) {
                int c = wn + nt * 8 + gID;
                uint2 bb = *(const uint2*)&Bs[c * AST + ks + 2 * tig];
                bf[nt][0] = bb.x; bf[nt][1] = bb.y;
            }
#pragma unroll
            for (int mt = 0; mt < 4; mt++)
#pragma unroll
                for (int nt = 0; nt < 4; nt++)
                    MMA_TF32(acc[mt][nt], af[mt][0], af[mt][1], af[mt][2], af[mt][3],
                             bf[nt][0], bf[nt][1]);
        }
        buf = (buf + 1) & 3;
    }

    const int pe = ((tig & 1) << 2) | (tig >> 1);   // perm8(2*tig)
#pragma unroll
    for (int mt = 0; mt < 4; mt++) {
        int r = row0 + wm + mt * 16 + gID;
#pragma unroll
        for (int nt = 0; nt < 4; nt++) {
            int c = col0 + wn + nt * 8 + 2 * tig;
            float b0v = bias[c], b1v = bias[c + 1];
            float v00 = acc[mt][nt][0] + b0v, v01 = acc[mt][nt][1] + b1v;
            float v10 = acc[mt][nt][2] + b0v, v11 = acc[mt][nt][3] + b1v;
            if (perm_round_out) {
                int p0 = (c & ~7) | pe;
                out[(size_t)r * N + p0]           = __uint_as_float(f2tf(v00));
                out[(size_t)r * N + p0 + 2]       = __uint_as_float(f2tf(v01));
                out[(size_t)(r + 8) * N + p0]     = __uint_as_float(f2tf(v10));
                out[(size_t)(r + 8) * N + p0 + 2] = __uint_as_float(f2tf(v11));
            } else {
                float2 v0 = {v00, v01};
                float2 v1 = {v10, v11};
                *(float2*)(out + (size_t)r * N + c) = v0;
                *(float2*)(out + (size_t)(r + 8) * N + c) = v1;
            }
        }
    }
}

// ---------------------------------------------------------------------------
// TF32 flash attention. qkv is tf32-exact + d-perm8 => Q/K frags are uint2.
// P stored perm8 in smem => PV A-frags uint2. V columns permuted => att_out
// lands in perm8 convention automatically (matches proj GEMM input).
// ---------------------------------------------------------------------------
__global__ __launch_bounds__(256) void attn_tc_kernel(
    const float* __restrict__ qkv,
    float* __restrict__ attn_w,
    float* __restrict__ att_out,
    float* __restrict__ ml,
    int write_attn)
{
    extern __shared__ unsigned smu[];
    unsigned* Qs = smu;                      // [128][QSTR]
    unsigned* Ks = Qs + 128 * QSTR;          // [64][KSTR]
    unsigned* Vs = Ks + 64 * KSTR;           // [64][VSTR]
    unsigned* Ps = Vs + 64 * VSTR;           // [128][QSTR]

    const int tid  = threadIdx.x;
    const int warp = tid >> 5, lane = tid & 31;
    const int gID  = lane >> 2, tig = lane & 3;
    const int qt = (Tt / 128 - 1) - blockIdx.x;
    const int h  = blockIdx.y;
    const int b  = blockIdx.z;
    const int q0 = qt * 128;
    const int row_w = warp * 16;
    const int pe = ((tig & 1) << 2) | (tig >> 1);   // perm8(2*tig)

    const float* Qg = qkv + ((size_t)b * Tt + q0) * C3 + h * Dd;
    const float* Kg = qkv + (size_t)b * Tt * C3 + Cc + h * Dd;
    const float* Vg = qkv + (size_t)b * Tt * C3 + 2 * Cc + h * Dd;

    // Q: tf32-exact & permuted already; *0.125 exact, position-independent
    for (int idx = tid; idx < 2048; idx += 256) {
        int q = idx >> 4, dc = (idx & 15) << 2;
        float4 v = *(const float4*)(Qg + (size_t)q * C3 + dc);
        unsigned* p = Qs + q * QSTR + dc;
        p[0] = __float_as_uint(v.x * 0.125f);
        p[1] = __float_as_uint(v.y * 0.125f);
        p[2] = __float_as_uint(v.z * 0.125f);
        p[3] = __float_as_uint(v.w * 0.125f);
    }

    float m0 = -1e30f, m1 = -1e30f, l0 = 0.f, l1 = 0.f;
    float o[8][4];
#pragma unroll
    for (int nt = 0; nt < 8; nt++)
#pragma unroll
        for (int i = 0; i < 4; i++) o[nt][i] = 0.f;

    const int r0g = q0 + row_w + gID;
    const int r1g = r0g + 8;
    const size_t wrow0 = ((size_t)(b * Hh + h) * Tt + r0g) * (size_t)Tt;
    const size_t wrow1 = wrow0 + 8 * (size_t)Tt;

    const int nkt = 2 * qt + 2;
    for (int kt = 0; kt < nkt; kt++) {
        const int j0 = kt * 64;
        __syncthreads();
        for (int idx = tid; idx < 1024; idx += 256) {
            int j = idx >> 4, dc = (idx & 15) << 2;
            cp16(Ks + j * KSTR + dc, Kg + (size_t)(j0 + j) * C3 + dc);
            cp16(Vs + j * VSTR + dc, Vg + (size_t)(j0 + j) * C3 + dc);
        }
        CP_COMMIT();
        CP_WAIT0();
        __syncthreads();

        float s[8][4];
#pragma unroll
        for (int nt = 0; nt < 8; nt++)
#pragma unroll
            for (int i = 0; i < 4; i++) s[nt][i] = 0.f;
#pragma unroll
        for (int ks = 0; ks < 8; ks++) {
            uint2 qlo = *(const uint2*)&Qs[(row_w + gID) * QSTR + ks * 8 + 2 * tig];
            uint2 qhi = *(const uint2*)&Qs[(row_w + gID + 8) * QSTR + ks * 8 + 2 * tig];
#pragma unroll
            for (int nt = 0; nt < 8; nt++) {
                uint2 kb = *(const uint2*)&Ks[(nt * 8 + gID) * KSTR + ks * 8 + 2 * tig];
                MMA_TF32(s[nt], qlo.x, qhi.x, qlo.y, qhi.y, kb.x, kb.y);
            }
        }

        if (kt >= 2 * qt) {
#pragma unroll
            for (int nt = 0; nt < 8; nt++) {
                int c = j0 + nt * 8 + 2 * tig;
                if (c     > r0g) s[nt][0] = -1e30f;
                if (c + 1 > r0g) s[nt][1] = -1e30f;
                if (c     > r1g) s[nt][2] = -1e30f;
                if (c + 1 > r1g) s[nt][3] = -1e30f;
            }
        }

        if (write_attn) {
#pragma unroll
            for (int nt = 0; nt < 8; nt++) {
                int c = j0 + nt * 8 + 2 * tig;
                float2 v0 = {s[nt][0], s[nt][1]};
                float2 v1 = {s[nt][2], s[nt][3]};
                *(float2*)(attn_w + wrow0 + c) = v0;
                *(float2*)(attn_w + wrow1 + c) = v1;
            }
        }

        float tm0 = -1e30f, tm1 = -1e30f;
#pragma unroll
        for (int nt = 0; nt < 8; nt++) {
            tm0 = fmaxf(tm0, fmaxf(s[nt][0], s[nt][1]));
            tm1 = fmaxf(tm1, fmaxf(s[nt][2], s[nt][3]));
        }
        tm0 = fmaxf(tm0, __shfl_xor_sync(0xffffffffu, tm0, 1));
        tm0 = fmaxf(tm0, __shfl_xor_sync(0xffffffffu, tm0, 2));
        tm1 = fmaxf(tm1, __shfl_xor_sync(0xffffffffu, tm1, 1));
        tm1 = fmaxf(tm1, __shfl_xor_sync(0xffffffffu, tm1, 2));

        float mn0 = fmaxf(m0, tm0), mn1 = fmaxf(m1, tm1);
        float f0 = __expf(m0 - mn0), f1 = __expf(m1 - mn1);
        float rs0 = 0.f, rs1 = 0.f;
#pragma unroll
        for (int nt = 0; nt < 8; nt++) {
            s[nt][0] = __expf(s[nt][0] - mn0);
            s[nt][1] = __expf(s[nt][1] - mn0);
            s[nt][2] = __expf(s[nt][2] - mn1);
            s[nt][3] = __expf(s[nt][3] - mn1);
            rs0 += s[nt][0] + s[nt][1];
            rs1 += s[nt][2] + s[nt][3];
        }
        rs0 += __shfl_xor_sync(0xffffffffu, rs0, 1);
        rs0 += __shfl_xor_sync(0xffffffffu, rs0, 2);
        rs1 += __shfl_xor_sync(0xffffffffu, rs1, 1);
        rs1 += __shfl_xor_sync(0xffffffffu, rs1, 2);
        l0 = l0 * f0 + rs0;  m0 = mn0;
        l1 = l1 * f1 + rs1;  m1 = mn1;
#pragma unroll
        for (int nt = 0; nt < 8; nt++) {
            o[nt][0] *= f0; o[nt][1] *= f0;
            o[nt][2] *= f1; o[nt][3] *= f1;
        }

        // P -> smem, perm8'd j layout (so PV A-frags are uint2)
#pragma unroll
        for (int nt = 0; nt < 8; nt++) {
            unsigned* p0 = Ps + (row_w + gID) * QSTR + nt * 8 + pe;
            unsigned* p1 = Ps + (row_w + gID + 8) * QSTR + nt * 8 + pe;
            p0[0] = f2tf(s[nt][0]);  p0[2] = f2tf(s[nt][1]);
            p1[0] = f2tf(s[nt][2]);  p1[2] = f2tf(s[nt][3]);
        }
        __syncthreads();

#pragma unroll
        for (int ks = 0; ks < 8; ks++) {
            uint2 plo = *(const uint2*)&Ps[(row_w + gID) * QSTR + ks * 8 + 2 * tig];
            uint2 phi = *(const uint2*)&Ps[(row_w + gID + 8) * QSTR + ks * 8 + 2 * tig];
#pragma unroll
            for (int nt = 0; nt < 8; nt++) {
                unsigned b0 = Vs[(ks * 8 + tig) * VSTR + nt * 8 + gID];
                unsigned b1 = Vs[(ks * 8 + tig + 4) * VSTR + nt * 8 + gID];
                MMA_TF32(o[nt], plo.x, phi.x, plo.y, phi.y, b0, b1);
            }
        }
    }

    // epilogue: columns are already perm8 positions (V was permuted) — write linear
    float invl0 = 1.f / l0, invl1 = 1.f / l1;
    float* op0 = att_out + ((size_t)b * Tt + r0g) * Cc + h * Dd;
    float* op1 = att_out + ((size_t)b * Tt + r1g) * Cc + h * Dd;
#pragma unroll
    for (int nt = 0; nt < 8; nt++) {
        int c = nt * 8 + 2 * tig;
        float2 v0 = {__uint_as_float(f2tf(o[nt][0] * invl0)),
                     __uint_as_float(f2tf(o[nt][1] * invl0))};
        float2 v1 = {__uint_as_float(f2tf(o[nt][2] * invl1)),
                     __uint_as_float(f2tf(o[nt][3] * invl1))};
        *(float2*)(op0 + c) = v0;
        *(float2*)(op1 + c) = v1;
    }
    if (tig == 0) {
        size_t row = (size_t)(b * Hh + h) * Tt + r0g;
        ml[row * 2] = m0;  ml[row * 2 + 1] = l0;
        ml[(row + 8) * 2] = m1;  ml[(row + 8) * 2 + 1] = l1;
    }
}

// ---------------------------------------------------------------------------
__global__ __launch_bounds__(256) void attn_norm_kernel(
    float* __restrict__ attn_w, const float* __restrict__ ml)
{
    const int row = blockIdx.x;
    const int q = row & (Tt - 1);
    const float mrow = ml[(size_t)row * 2];
    const float invl = 1.f / ml[(size_t)row * 2 + 1];
    float* base = attn_w + (size_t)row * Tt;

    for (int c0 = threadIdx.x * 4; c0 < Tt; c0 += 256 * 4) {
        if (c0 > q) {
            float4 z = {0.f, 0.f, 0.f, 0.f};
            *(float4*)(base + c0) = z;
        } else {
            float4 s = *(const float4*)(base + c0);
            float4 w;
            w.x = (c0 + 0 > q) ? 0.f : __expf(s.x - mrow) * invl;
            w.y = (c0 + 1 > q) ? 0.f : __expf(s.y - mrow) * invl;
            w.z = (c0 + 2 > q) ? 0.f : __expf(s.z - mrow) * invl;
            w.w = (c0 + 3 > q) ? 0.f : __expf(s.w - mrow) * invl;
            *(float4*)(base + c0) = w;
        }
    }
}

// ---------------------------------------------------------------------------
extern "C" void kernel_launch(void* const* d_in, const int* in_sizes, int n_in,
                              void* d_out, int out_size)
{
    const float* x     = (const float*)d_in[0];
    const float* w_qkv = (const float*)d_in[1];
    const float* b_qkv = (const float*)d_in[2];
    const float* w_o   = (const float*)d_in[3];
    const float* b_o   = (const float*)d_in[4];
    float* out = (float*)d_out;

    float *qkv_ptr, *att_ptr, *ml_ptr, *x_ptr, *wqkv_ptr, *wo_ptr;
    cudaGetSymbolAddress((void**)&qkv_ptr, g_qkv);
    cudaGetSymbolAddress((void**)&att_ptr, g_att);
    cudaGetSymbolAddress((void**)&ml_ptr, g_ml);
    cudaGetSymbolAddress((void**)&x_ptr, g_x);
    cudaGetSymbolAddress((void**)&wqkv_ptr, g_wqkv);
    cudaGetSymbolAddress((void**)&wo_ptr, g_wo);

    const size_t o_elems    = (size_t)Bb * Tt * Cc;
    const size_t attn_elems = (size_t)Bb * Hh * Tt * (size_t)Tt;
    int write_attn = ((size_t)out_size >= o_elems + attn_elems) ? 1 : 0;
    float* attn_w_ptr = write_attn ? (out + o_elems) : nullptr;

    const int gemm_smem = GEMM_SMEM_W * sizeof(float);                   // 98304
    const int attn_smem = (128 * QSTR + 64 * KSTR + 64 * VSTR + 128 * QSTR)
                          * sizeof(unsigned);                             // 110592
    cudaFuncSetAttribute(gemm_tc_kernel,
                         cudaFuncAttributeMaxDynamicSharedMemorySize, gemm_smem);
    cudaFuncSetAttribute(attn_tc_kernel,
                         cudaFuncAttributeMaxDynamicSharedMemorySize, attn_smem);

    // 0) prep: round + perm8 x; transpose + round + perm8 weights
    {
        int nx = BT * Cc;
        prep_x_kernel<<<nx / 1024, 256>>>(x, x_ptr, nx);
        dim3 blk(32, 8);
        prep_wt_kernel<<<dim3(C3 / 32, Cc / 32), blk>>>(w_qkv, wqkv_ptr, Cc, C3);
        prep_wt_kernel<<<dim3(Cc / 32, Cc / 32), blk>>>(w_o, wo_ptr, Cc, Cc);
    }
    // 1) QKV projection -> perm8'd, tf32-exact qkv
    {
        dim3 grid(C3 / 128, BT / 128);
        gemm_tc_kernel<<<grid, 256, gemm_smem>>>(x_ptr, wqkv_ptr, b_qkv, qkv_ptr,
                                                 BT, C3, Cc, 1);
    }
    // 2) causal attention (raw scores + m,l + perm8'd attn_v)
    {
        dim3 grid(Tt / 128, Hh, Bb);
        attn_tc_kernel<<<grid, 256, attn_smem>>>(qkv_ptr, attn_w_ptr, att_ptr,
                                                 ml_ptr, write_attn);
    }
    // 3) normalize attn_w
    if (write_attn) {
        attn_norm_kernel<<<Bb * Hh * Tt, 256>>>(attn_w_ptr, ml_ptr);
    }
    // 4) output projection (unpermuted output)
    {
        dim3 grid(Cc / 128, BT / 128);
        gemm_tc_kernel<<<grid, 256, gemm_smem>>>(att_ptr, wo_ptr, b_o, out,
                                                 BT, Cc, Cc, 0);
    }
}